// round 2
// baseline (speedup 1.0000x reference)
#include <cuda_runtime.h>

// QLayer analytic form (derivation in R0):
//   out[b][w] = prod_{j<=w} cos^2(x[b][j])
//
// 512 x 16 = 8192 outputs. One thread per element, __cosf (single MUFU.COS,
// inputs are N(0,1) so fast-path range reduction is plenty accurate),
// 16-lane segmented inclusive prefix product via 4x shfl_up.
// 64 blocks x 128 threads -> 64 SMs, minimal per-SM tail.

#define NQ    16
#define BATCH 512

__global__ void __launch_bounds__(128, 1)
qlayer_kernel(const float* __restrict__ x, float* __restrict__ out)
{
    int idx = blockIdx.x * blockDim.x + threadIdx.x;   // 0 .. 8191
    int seg_lane = threadIdx.x & 15;                   // position within 16-wire row

    float cc = __cosf(x[idx]);
    float v = cc * cc;

    // Inclusive prefix product over the 16-lane segment (rows are 16-aligned
    // within each warp: lanes [0,16) = row 2k, lanes [16,32) = row 2k+1).
    #pragma unroll
    for (int off = 1; off < 16; off <<= 1) {
        float o = __shfl_up_sync(0xffffffffu, v, off);
        if (seg_lane >= off) v *= o;
    }

    out[idx] = v;
}

extern "C" void kernel_launch(void* const* d_in, const int* in_sizes, int n_in,
                              void* d_out, int out_size)
{
    const float* x = (const float*)d_in[0];
    // d_in[1] = params (RZ angles): diagonal gates, analytically irrelevant to <Z>.
    float* out = (float*)d_out;

    qlayer_kernel<<<64, 128>>>(x, out);
}

// round 3
// speedup vs baseline: 1.0142x; 1.0142x over previous
#include <cuda_runtime.h>

// QLayer analytic form (derivation in R0):
//   out[b][w] = prod_{j<=w} cos^2(x[b][j])       (512 x 16)
//
// Vectorized: 2048 threads, one float4 (4 consecutive wires) each.
// Row of 16 wires = 4 lanes. Per-thread serial prefix over the 4 registers,
// then a 4-lane segmented scan (3 shfls) to stitch lane-prefixes together.

#define TOTAL4 2048   // 8192 floats / 4

__global__ void __launch_bounds__(128, 1)
qlayer_kernel(const float4* __restrict__ x4, float4* __restrict__ out4)
{
    int idx = blockIdx.x * blockDim.x + threadIdx.x;   // 0 .. 2047
    int seg = threadIdx.x & 3;                         // lane within 4-lane row

    float4 xv = x4[idx];

    float c0 = __cosf(xv.x), c1 = __cosf(xv.y), c2 = __cosf(xv.z), c3 = __cosf(xv.w);
    float v0 = c0 * c0;
    float v1 = v0 * (c1 * c1);
    float v2 = v1 * (c2 * c2);
    float v3 = v2 * (c3 * c3);     // thread-local inclusive prefix; v3 = chunk total

    // Inclusive scan of chunk totals over the 4-lane segment (2 rounds),
    // then shift to exclusive.
    float t = v3;
    float o1 = __shfl_up_sync(0xffffffffu, t, 1);
    if (seg >= 1) t *= o1;
    float o2 = __shfl_up_sync(0xffffffffu, t, 2);
    if (seg >= 2) t *= o2;
    float p = __shfl_up_sync(0xffffffffu, t, 1);       // exclusive prefix
    if (seg == 0) p = 1.0f;

    float4 r;
    r.x = p * v0;
    r.y = p * v1;
    r.z = p * v2;
    r.w = p * v3;
    out4[idx] = r;
}

extern "C" void kernel_launch(void* const* d_in, const int* in_sizes, int n_in,
                              void* d_out, int out_size)
{
    const float4* x = (const float4*)d_in[0];
    // d_in[1] = params (RZ angles): diagonal, analytically irrelevant to <Z>.
    float4* out = (float4*)d_out;

    qlayer_kernel<<<TOTAL4 / 128, 128>>>(x, out);
}

// round 4
// speedup vs baseline: 1.1031x; 1.0876x over previous
#include <cuda_runtime.h>

// QLayer analytic form (derivation in R0):
//   out[b][w] = prod_{j<=w} cos^2(x[b][j])       (512 x 16)
//
// float4-vectorized: 2048 threads (one float4 = 4 wires each), spread over
// 64 blocks x 32 threads (one warp per block, 64 SMs, no barriers).
// Per-thread serial prefix over its 4 values, then the 4-lane-segment
// exclusive prefix via 3 INDEPENDENT indexed shfls (pipelined, ~26 cyc total)
// instead of a dependent shfl_up chain (~78 cyc).

#define TOTAL4 2048   // 8192 floats / 4

__global__ void __launch_bounds__(32, 1)
qlayer_kernel(const float4* __restrict__ x4, float4* __restrict__ out4)
{
    int idx = blockIdx.x * blockDim.x + threadIdx.x;   // 0 .. 2047
    int seg  = threadIdx.x & 3;                        // lane within 4-lane row
    int base = threadIdx.x & ~3;                       // first lane of this row

    float4 xv = x4[idx];

    float c0 = __cosf(xv.x), c1 = __cosf(xv.y), c2 = __cosf(xv.z), c3 = __cosf(xv.w);
    float v0 = c0 * c0;
    float v1 = v0 * (c1 * c1);
    float v2 = v1 * (c2 * c2);
    float v3 = v2 * (c3 * c3);     // chunk total

    // Exclusive prefix of chunk totals across the 4-lane segment:
    // three independent shfls (no serial dependence), then predicated combine.
    float t0 = __shfl_sync(0xffffffffu, v3, base + 0);
    float t1 = __shfl_sync(0xffffffffu, v3, base + 1);
    float t2 = __shfl_sync(0xffffffffu, v3, base + 2);

    float p = 1.0f;
    if (seg >= 1) p = t0;
    if (seg >= 2) p *= t1;
    if (seg >= 3) p *= t2;

    float4 r;
    r.x = p * v0;
    r.y = p * v1;
    r.z = p * v2;
    r.w = p * v3;
    out4[idx] = r;
}

extern "C" void kernel_launch(void* const* d_in, const int* in_sizes, int n_in,
                              void* d_out, int out_size)
{
    const float4* x = (const float4*)d_in[0];
    // d_in[1] = params (RZ angles): diagonal, analytically irrelevant to <Z>.
    float4* out = (float4*)d_out;

    qlayer_kernel<<<64, 32>>>(x, out);
}

// round 5
// speedup vs baseline: 1.4861x; 1.3472x over previous
#include <cuda_runtime.h>

// QLayer analytic form (derivation in R0):
//   Circuit = per-wire RX(x_w) RY(x_w) RZ(theta_w) on |0>, then CNOT ladder
//   0->1 ... 14->15, measure Z everywhere. Heisenberg-picture pullback of Z_w
//   through the ladder gives Z_0 Z_1 ... Z_w on the (product) pre-CNOT state:
//     out[b][w] = prod_{j<=w} cos^2(x[b][j])          (512 x 16)
//
// 8192 threads, one per output element, spread over 128 blocks x 64 threads
// (128 SMs, 2 warps each — widest wave-1 spread, minimal drain tail).
// __cosf = single MUFU.COS (inputs ~N(0,1), fast range reduction is exact
// enough: measured rel_err 6.7e-7 vs 1e-3 threshold).
// 16-lane segmented inclusive prefix product via 4x shfl_up.

__global__ void __launch_bounds__(64, 1)
qlayer_kernel(const float* __restrict__ x, float* __restrict__ out)
{
    int idx = blockIdx.x * blockDim.x + threadIdx.x;   // 0 .. 8191
    int seg_lane = threadIdx.x & 15;                   // position within 16-wire row

    float cc = __cosf(x[idx]);
    float v = cc * cc;

    // Inclusive prefix product over the 16-lane segment (segments are
    // 16-aligned within each warp).
    #pragma unroll
    for (int off = 1; off < 16; off <<= 1) {
        float o = __shfl_up_sync(0xffffffffu, v, off);
        if (seg_lane >= off) v *= o;
    }

    out[idx] = v;
}

extern "C" void kernel_launch(void* const* d_in, const int* in_sizes, int n_in,
                              void* d_out, int out_size)
{
    const float* x = (const float*)d_in[0];
    // d_in[1] = params (RZ angles): diagonal gates, analytically irrelevant to <Z>.
    float* out = (float*)d_out;

    qlayer_kernel<<<128, 64>>>(x, out);
}

// round 6
// speedup vs baseline: 1.4965x; 1.0070x over previous
#include <cuda_runtime.h>

// QLayer analytic form (derivation in R0):
//   Heisenberg pullback of Z_w through the CNOT ladder = Z_0 Z_1 ... Z_w on
//   the product pre-CNOT state:
//     out[b][w] = prod_{j<=w} cos^2(x[b][j])          (512 x 16)
//
// 4096 threads (one float2 = 2 wires each), 128 blocks x 32 threads:
// wave-1 fits 148 SMs with the widest spread (per R5's measured win),
// one warp per block (no second-warp arbitration in the tail).
// Row of 16 wires = 8-lane segment -> 3 shfl_up rounds (vs 4 scalar).
// __cosf = single MUFU.COS; measured rel_err 6.7e-7 vs 1e-3 threshold.

__global__ void __launch_bounds__(32, 1)
qlayer_kernel(const float2* __restrict__ x2, float2* __restrict__ out2)
{
    int idx = blockIdx.x * blockDim.x + threadIdx.x;   // 0 .. 4095
    int seg = threadIdx.x & 7;                         // lane within 8-lane row

    float2 xv = x2[idx];
    float c0 = __cosf(xv.x);
    float c1 = __cosf(xv.y);
    float v0 = c0 * c0;
    float v1 = v0 * (c1 * c1);     // thread-local inclusive prefix; v1 = pair total

    // Inclusive scan of pair totals across the 8-lane segment (3 rounds),
    // then shift to exclusive.
    float t = v1;
    #pragma unroll
    for (int off = 1; off < 8; off <<= 1) {
        float o = __shfl_up_sync(0xffffffffu, t, off);
        if (seg >= off) t *= o;
    }
    float p = __shfl_up_sync(0xffffffffu, t, 1);       // exclusive prefix
    if (seg == 0) p = 1.0f;

    float2 r;
    r.x = p * v0;
    r.y = p * v1;
    out2[idx] = r;
}

extern "C" void kernel_launch(void* const* d_in, const int* in_sizes, int n_in,
                              void* d_out, int out_size)
{
    const float2* x = (const float2*)d_in[0];
    // d_in[1] = params (RZ angles): diagonal gates, analytically irrelevant to <Z>.
    float2* out = (float2*)d_out;

    qlayer_kernel<<<128, 32>>>(x, out);
}